// round 2
// baseline (speedup 1.0000x reference)
#include <cuda_runtime.h>
#include <cstdint>

// T=4 tables, E=1,000,000 rows/table, D=128 dims, B=8192 bags, L=32 bag length
// indices: [T, B, L] (int32 OR int64 — detected at runtime)
// weights: fp32 [T, E, D]; output: fp32 [B, T*D]
// out[b, t*D + d] = sum_l weights[t, indices[t,b,l], d]

#define T_TABLES 4
#define E_ROWS   1000000
#define D_DIM    128
#define B_BATCH  8192
#define L_BAG    32

// 1 = indices are int64, 0 = int32. Set by probe kernel each launch (deterministic).
__device__ int g_idx_is64;

__global__ void probe_idx_dtype(const long long* __restrict__ idx)
{
    if (threadIdx.x == 0 && blockIdx.x == 0) {
        int ok64 = 1;
        // If data is really int32, hi-words are random row ids in [0,1M):
        // the chance all 128 probed int64 values land in [0,E) is ~0.
        for (int i = 0; i < 128; ++i) {
            long long v = idx[i];
            if (v < 0 || v >= E_ROWS) { ok64 = 0; break; }
        }
        g_idx_is64 = ok64;
    }
}

// One warp per (t, b) bag. lane l holds indices[t,b,l]; broadcast via shfl.
// Each lane accumulates a float4: lane covers dims [4*lane, 4*lane+4).
__global__ __launch_bounds__(256) void embbag_kernel(
    const void*  __restrict__ indices_raw,   // [T*B*L] int32 or int64
    const float* __restrict__ weights,       // [T*E*D]
    float*       __restrict__ out)           // [B*T*D]
{
    const int warp_id = (blockIdx.x * blockDim.x + threadIdx.x) >> 5;
    const int lane    = threadIdx.x & 31;
    if (warp_id >= T_TABLES * B_BATCH) return;

    const int t = warp_id >> 13;            // / B_BATCH (8192)
    const int b = warp_id & (B_BATCH - 1);

    // Each lane loads one of the 32 bag indices (coalesced).
    const size_t idx_off = (size_t)warp_id * L_BAG + lane;
    long long my_idx;
    if (g_idx_is64) {
        my_idx = ((const long long*)indices_raw)[idx_off];
    } else {
        my_idx = (long long)((const int*)indices_raw)[idx_off];
    }

    const float4* __restrict__ wbase =
        reinterpret_cast<const float4*>(weights) + (size_t)t * E_ROWS * (D_DIM / 4);

    float4 acc = make_float4(0.f, 0.f, 0.f, 0.f);

    #pragma unroll
    for (int l = 0; l < L_BAG; ++l) {
        const long long row = __shfl_sync(0xffffffffu, my_idx, l);
        const float4 v = __ldg(wbase + (size_t)row * (D_DIM / 4) + lane);
        acc.x += v.x; acc.y += v.y; acc.z += v.z; acc.w += v.w;
    }

    float4* __restrict__ obase =
        reinterpret_cast<float4*>(out) +
        (size_t)b * (T_TABLES * D_DIM / 4) + (size_t)t * (D_DIM / 4);
    obase[lane] = acc;
}

extern "C" void kernel_launch(void* const* d_in, const int* in_sizes, int n_in,
                              void* d_out, int out_size)
{
    // Identify inputs by element count (robust to metadata ordering):
    // indices: T*B*L = 1,048,576 ; weights: T*E*D = 512,000,000
    const void*  indices = d_in[0];
    const float* weights = (const float*)d_in[1];
    if (n_in >= 2) {
        long long s0 = in_sizes[0], s1 = in_sizes[1];
        if (s0 > s1) {  // d_in[0] is the big weights buffer
            weights = (const float*)d_in[0];
            indices = d_in[1];
        }
    }
    float* out = (float*)d_out;

    probe_idx_dtype<<<1, 32>>>((const long long*)indices);

    const int total_warps = T_TABLES * B_BATCH;            // 32768
    const int threads     = 256;                            // 8 warps/block
    const int blocks      = (total_warps * 32) / threads;   // 4096

    embbag_kernel<<<blocks, threads>>>(indices, weights, out);
}